// round 1
// baseline (speedup 1.0000x reference)
#include <cuda_runtime.h>
#include <math.h>

// Problem constants
#define B_  64
#define T_  512
#define H_  1024
#define U_  1024
#define M_  (B_ * T_)          // 32768 rows of the big GEMM

// GEMM tiling
#define BM 128
#define BN 128
#define BK 16
#define AS_STRIDE 132          // padded to kill transposed-store bank conflicts (mod-32 friendly, float4-aligned)
#define KTILES (H_ / BK)       // 64
#define NBLK   (U_ / BN)       // 8 column blocks

// Scratch: per-(row, col-block) partial scores. Fully overwritten each launch -> deterministic, no zeroing needed.
__device__ float g_partial[M_ * NBLK];

// ---------------------------------------------------------------------------
// Kernel 1: fused  partial_score[m, nb] = sum_{u in colblock nb} tanh(enc@Wh + bh)[m,u] * Wv[u]
// A = enc_output as [M, H] row-major, Bmat = Wh [H, U] row-major.
// ---------------------------------------------------------------------------
__global__ __launch_bounds__(256, 2)
void k_gemm_tanh_dot(const float* __restrict__ A,
                     const float* __restrict__ Bmat,
                     const float* __restrict__ bh,
                     const float* __restrict__ Wv)
{
    __shared__ float As[BK][AS_STRIDE];   // stored transposed: As[k][m]
    __shared__ float Bs[BK][BN];          // Bs[k][n]

    const int tid = threadIdx.x;
    const int tx  = tid & 15;             // 0..15  (col group)
    const int ty  = tid >> 4;             // 0..15  (row group)

    const int rowBase = blockIdx.y * BM;
    const int colBase = blockIdx.x * BN;

    const float* Ag = A + rowBase * H_;
    const float* Bg = Bmat + colBase;

    // Load-index decomposition (two float4 per thread per tile for each of A and B)
    const int aRow0 = tid >> 2,        aC0 = (tid & 3) * 4;
    const int aRow1 = (tid + 256) >> 2, aC1 = ((tid + 256) & 3) * 4;
    const int bRow0 = tid >> 5,        bC0 = (tid & 31) * 4;
    const int bRow1 = (tid + 256) >> 5, bC1 = ((tid + 256) & 31) * 4;

    float acc[8][8];
#pragma unroll
    for (int i = 0; i < 8; i++)
#pragma unroll
        for (int j = 0; j < 8; j++) acc[i][j] = 0.0f;

    // --- prologue: load tile 0 into smem ---
    {
        float4 va0 = *(const float4*)(Ag + aRow0 * H_ + aC0);
        float4 va1 = *(const float4*)(Ag + aRow1 * H_ + aC1);
        float4 vb0 = *(const float4*)(Bg + bRow0 * U_ + bC0);
        float4 vb1 = *(const float4*)(Bg + bRow1 * U_ + bC1);
        As[aC0 + 0][aRow0] = va0.x; As[aC0 + 1][aRow0] = va0.y;
        As[aC0 + 2][aRow0] = va0.z; As[aC0 + 3][aRow0] = va0.w;
        As[aC1 + 0][aRow1] = va1.x; As[aC1 + 1][aRow1] = va1.y;
        As[aC1 + 2][aRow1] = va1.z; As[aC1 + 3][aRow1] = va1.w;
        *(float4*)&Bs[bRow0][bC0] = vb0;
        *(float4*)&Bs[bRow1][bC1] = vb1;
    }
    __syncthreads();

    for (int kt = 0; kt < KTILES; kt++) {
        float4 na0, na1, nb0, nb1;
        const bool more = (kt + 1 < KTILES);
        if (more) {
            const int k0 = (kt + 1) * BK;
            na0 = *(const float4*)(Ag + aRow0 * H_ + k0 + aC0);
            na1 = *(const float4*)(Ag + aRow1 * H_ + k0 + aC1);
            nb0 = *(const float4*)(Bg + (k0 + bRow0) * U_ + bC0);
            nb1 = *(const float4*)(Bg + (k0 + bRow1) * U_ + bC1);
        }

#pragma unroll
        for (int k = 0; k < BK; k++) {
            float a[8], b[8];
            *(float4*)(a)     = *(const float4*)&As[k][ty * 8];
            *(float4*)(a + 4) = *(const float4*)&As[k][ty * 8 + 4];
            *(float4*)(b)     = *(const float4*)&Bs[k][tx * 8];
            *(float4*)(b + 4) = *(const float4*)&Bs[k][tx * 8 + 4];
#pragma unroll
            for (int i = 0; i < 8; i++)
#pragma unroll
                for (int j = 0; j < 8; j++)
                    acc[i][j] = fmaf(a[i], b[j], acc[i][j]);
        }
        __syncthreads();
        if (more) {
            As[aC0 + 0][aRow0] = na0.x; As[aC0 + 1][aRow0] = na0.y;
            As[aC0 + 2][aRow0] = na0.z; As[aC0 + 3][aRow0] = na0.w;
            As[aC1 + 0][aRow1] = na1.x; As[aC1 + 1][aRow1] = na1.y;
            As[aC1 + 2][aRow1] = na1.z; As[aC1 + 3][aRow1] = na1.w;
            *(float4*)&Bs[bRow0][bC0] = nb0;
            *(float4*)&Bs[bRow1][bC1] = nb1;
            __syncthreads();
        }
    }

    // --- fused epilogue: s[i] = sum_j tanh(acc + bh) * Wv, then reduce across tx ---
    const int cb = colBase + tx * 8;
    float wv[8], bias[8];
#pragma unroll
    for (int j = 0; j < 8; j++) { wv[j] = Wv[cb + j]; bias[j] = bh[cb + j]; }

    float s[8];
#pragma unroll
    for (int i = 0; i < 8; i++) {
        float t = 0.0f;
#pragma unroll
        for (int j = 0; j < 8; j++)
            t = fmaf(tanhf(acc[i][j] + bias[j]), wv[j], t);
        s[i] = t;
    }

    // reduction across the 16 tx lanes that share each row (reuse As memory)
    float* red = &As[0][0];   // 2112 floats available, need 128*16 = 2048
#pragma unroll
    for (int i = 0; i < 8; i++)
        red[(ty * 8 + i) * 16 + tx] = s[i];
    __syncthreads();

    if (tid < BM) {
        float tot = 0.0f;
#pragma unroll
        for (int x = 0; x < 16; x++) tot += red[tid * 16 + x];
        g_partial[(rowBase + tid) * NBLK + blockIdx.x] = tot;
    }
}

// ---------------------------------------------------------------------------
// Kernel 2: per-batch softmax over T=512 (dec/bias terms cancel in softmax)
// ---------------------------------------------------------------------------
__global__ void k_softmax(float* __restrict__ attn_out)
{
    const int b = blockIdx.x;
    const int t = threadIdx.x;        // 512 threads
    __shared__ float sm[T_];

    const float* p = g_partial + (b * T_ + t) * NBLK;
    float sc = 0.0f;
#pragma unroll
    for (int i = 0; i < NBLK; i++) sc += p[i];

    sm[t] = sc;
    __syncthreads();
    for (int o = T_ / 2; o > 0; o >>= 1) {
        if (t < o) sm[t] = fmaxf(sm[t], sm[t + o]);
        __syncthreads();
    }
    const float mx = sm[0];
    __syncthreads();

    const float e = expf(sc - mx);
    sm[t] = e;
    __syncthreads();
    for (int o = T_ / 2; o > 0; o >>= 1) {
        if (t < o) sm[t] += sm[t + o];
        __syncthreads();
    }
    attn_out[b * T_ + t] = e / sm[0];
}

// ---------------------------------------------------------------------------
// Kernel 3: context[b,h] = sum_t attn[b,t] * enc[b,t,h]   (bandwidth-bound)
// ---------------------------------------------------------------------------
__global__ __launch_bounds__(256)
void k_context(const float* __restrict__ enc,
               const float* __restrict__ attn,
               float* __restrict__ ctx)
{
    const int b = blockIdx.y;
    const int h = blockIdx.x * 256 + threadIdx.x;

    __shared__ float a[T_];
    a[threadIdx.x]       = attn[b * T_ + threadIdx.x];
    a[threadIdx.x + 256] = attn[b * T_ + 256 + threadIdx.x];
    __syncthreads();

    const float* e = enc + (size_t)b * T_ * H_ + h;
    float acc0 = 0.f, acc1 = 0.f, acc2 = 0.f, acc3 = 0.f;
    float acc4 = 0.f, acc5 = 0.f, acc6 = 0.f, acc7 = 0.f;
#pragma unroll 2
    for (int t = 0; t < T_; t += 8) {
        acc0 = fmaf(a[t + 0], e[(t + 0) * H_], acc0);
        acc1 = fmaf(a[t + 1], e[(t + 1) * H_], acc1);
        acc2 = fmaf(a[t + 2], e[(t + 2) * H_], acc2);
        acc3 = fmaf(a[t + 3], e[(t + 3) * H_], acc3);
        acc4 = fmaf(a[t + 4], e[(t + 4) * H_], acc4);
        acc5 = fmaf(a[t + 5], e[(t + 5) * H_], acc5);
        acc6 = fmaf(a[t + 6], e[(t + 6) * H_], acc6);
        acc7 = fmaf(a[t + 7], e[(t + 7) * H_], acc7);
    }
    ctx[b * H_ + h] = ((acc0 + acc1) + (acc2 + acc3)) + ((acc4 + acc5) + (acc6 + acc7));
}

// ---------------------------------------------------------------------------
// Launch. Inputs (metadata order): dec_hidden, enc_output, Wh, bh, Ws, bs, Wv, bv.
// dec_hidden/Ws/bs/bv are mathematically irrelevant (constant shift cancels in softmax).
// Output: [context (64*1024) | attn (64*512)] fp32.
// ---------------------------------------------------------------------------
extern "C" void kernel_launch(void* const* d_in, const int* in_sizes, int n_in,
                              void* d_out, int out_size)
{
    (void)in_sizes; (void)n_in; (void)out_size;
    const float* enc = (const float*)d_in[1];
    const float* Wh  = (const float*)d_in[2];
    const float* bh  = (const float*)d_in[3];
    const float* Wv  = (const float*)d_in[6];

    float* out  = (float*)d_out;
    float* ctx  = out;                 // [B, H]
    float* attn = out + B_ * H_;       // [B, T]

    k_gemm_tanh_dot<<<dim3(NBLK, M_ / BM), 256>>>(enc, Wh, bh, Wv);
    k_softmax<<<B_, T_>>>(attn);
    k_context<<<dim3(H_ / 256, B_), 256>>>(enc, attn, ctx);
}

// round 3
// speedup vs baseline: 1.8561x; 1.8561x over previous
#include <cuda_runtime.h>
#include <cuda_bf16.h>
#include <cstdint>
#include <math.h>

// ---------------- problem constants ----------------
#define B_  64
#define T_  512
#define H_  1024
#define U_  1024
#define M_  (B_ * T_)          // 32768
#define NBLK 8                 // U_/128 column blocks

// ---------------- GEMM tiling ----------------
#define BM 128
#define BN 128
#define KSTEP 16
#define NK (H_ / KSTEP)        // 64 k-steps
#define ROWB 48                // padded smem row bytes (16 bf16 data + 16B pad) -> conflict-free frags
#define TILEB (128 * ROWB)     // 6144 B per tile
#define STAGEB (4 * TILEB)     // Ah, Al, Bh, Bl = 24576 B per stage
#define PIPE 4                 // cp.async pipeline depth
#define SMEM_TOTAL (PIPE * STAGEB)   // 98304 B

// ---------------- device scratch ----------------
__device__ __nv_bfloat16 g_Ah[(size_t)M_ * H_];
__device__ __nv_bfloat16 g_Al[(size_t)M_ * H_];
__device__ __nv_bfloat16 g_Bh[(size_t)U_ * H_];   // Wh^T as [n][k]
__device__ __nv_bfloat16 g_Bl[(size_t)U_ * H_];
__device__ float g_partial[(size_t)M_ * NBLK];

// ---------------- helpers ----------------
__device__ __forceinline__ uint32_t smem_u32(const void* p) {
    uint32_t a;
    asm("{ .reg .u64 t; cvta.to.shared.u64 t, %1; cvt.u32.u64 %0, t; }" : "=r"(a) : "l"(p));
    return a;
}
__device__ __forceinline__ void cp16(uint32_t dst, const void* src) {
    asm volatile("cp.async.cg.shared.global [%0], [%1], 16;" :: "r"(dst), "l"(src));
}
__device__ __forceinline__ void cp_commit() { asm volatile("cp.async.commit_group;" ::: "memory"); }
template <int N_> __device__ __forceinline__ void cp_wait() {
    asm volatile("cp.async.wait_group %0;" :: "n"(N_) : "memory");
}
__device__ __forceinline__ uint32_t lds32(uint32_t a) {
    uint32_t v;
    asm volatile("ld.shared.b32 %0, [%1];" : "=r"(v) : "r"(a));
    return v;
}
__device__ __forceinline__ void mma16816(float* d, const uint32_t* a, uint32_t b0, uint32_t b1) {
    asm volatile(
        "mma.sync.aligned.m16n8k16.row.col.f32.bf16.bf16.f32 "
        "{%0,%1,%2,%3},{%4,%5,%6,%7},{%8,%9},{%0,%1,%2,%3};"
        : "+f"(d[0]), "+f"(d[1]), "+f"(d[2]), "+f"(d[3])
        : "r"(a[0]), "r"(a[1]), "r"(a[2]), "r"(a[3]), "r"(b0), "r"(b1));
}
__device__ __forceinline__ float fast_tanh(float x) {
    float ax = fabsf(x);
    float e  = __expf(2.0f * ax);
    float r  = 1.0f - __fdividef(2.0f, e + 1.0f);
    return copysignf(r, x);
}

// ---------------------------------------------------------------------------
// Kernel 0a: split enc fp32 -> bf16 hi/lo
// ---------------------------------------------------------------------------
__global__ __launch_bounds__(256)
void k_convA(const float* __restrict__ A)
{
    size_t i = ((size_t)blockIdx.x * 256 + threadIdx.x) * 4;
    float4 v = *(const float4*)(A + i);
    __nv_bfloat16 h0 = __float2bfloat16(v.x), h1 = __float2bfloat16(v.y);
    __nv_bfloat16 h2 = __float2bfloat16(v.z), h3 = __float2bfloat16(v.w);
    __nv_bfloat16 l0 = __float2bfloat16(v.x - __bfloat162float(h0));
    __nv_bfloat16 l1 = __float2bfloat16(v.y - __bfloat162float(h1));
    __nv_bfloat16 l2 = __float2bfloat16(v.z - __bfloat162float(h2));
    __nv_bfloat16 l3 = __float2bfloat16(v.w - __bfloat162float(h3));
    __nv_bfloat162* ph = (__nv_bfloat162*)(g_Ah + i);
    __nv_bfloat162* pl = (__nv_bfloat162*)(g_Al + i);
    ph[0] = __nv_bfloat162(h0, h1); ph[1] = __nv_bfloat162(h2, h3);
    pl[0] = __nv_bfloat162(l0, l1); pl[1] = __nv_bfloat162(l2, l3);
}

// ---------------------------------------------------------------------------
// Kernel 0b: transpose+split Wh [K,N] fp32 -> g_Bh/g_Bl [N,K] bf16
// ---------------------------------------------------------------------------
__global__ __launch_bounds__(256)
void k_convB(const float* __restrict__ Wh)
{
    __shared__ float tile[32][33];
    const int k0 = blockIdx.y * 32, n0 = blockIdx.x * 32;
    const int tx = threadIdx.x, ty = threadIdx.y;   // 32 x 8
#pragma unroll
    for (int r = 0; r < 4; r++)
        tile[ty + r * 8][tx] = Wh[(size_t)(k0 + ty + r * 8) * U_ + n0 + tx];
    __syncthreads();
#pragma unroll
    for (int r = 0; r < 4; r++) {
        int n = n0 + ty + r * 8;
        int k = k0 + tx;
        float v = tile[tx][ty + r * 8];
        __nv_bfloat16 h = __float2bfloat16(v);
        __nv_bfloat16 l = __float2bfloat16(v - __bfloat162float(h));
        g_Bh[(size_t)n * H_ + k] = h;
        g_Bl[(size_t)n * H_ + k] = l;
    }
}

// ---------------------------------------------------------------------------
// Kernel 1: bf16 split GEMM via mma.sync.m16n8k16 + fused tanh-dot epilogue.
// C[m,n] = sum_k enc[m,k]*Wh[k,n] via Ah*Bh + Ah*Bl + Al*Bh
// partial[m, nb] = sum_{n in col-block nb} tanh(C + bh[n]) * Wv[n]
// ---------------------------------------------------------------------------
__global__ __launch_bounds__(256, 2)
void k_gemm_mma(const float* __restrict__ bh, const float* __restrict__ Wv)
{
    extern __shared__ char smem[];
    const uint32_t sb = smem_u32(smem);

    const int tid  = threadIdx.x;
    const int warp = tid >> 5;
    const int lane = tid & 31;
    const int g    = lane >> 2;       // groupID
    const int tig  = lane & 3;        // thread-in-group
    const int warpM = warp >> 1;      // 0..3
    const int warpN = warp & 1;       // 0..1

    const int rowBase = blockIdx.y * BM;
    const int colBase = blockIdx.x * BN;

    // per-thread stage-load indices (1x 16B chunk per tile, 4 tiles)
    const int lrow  = tid >> 1;           // 0..127
    const int lhalf = tid & 1;            // which 16B of the 32B row
    const size_t gOffA = (size_t)(rowBase + lrow) * H_ + lhalf * 8;
    const size_t gOffB = (size_t)(colBase + lrow) * H_ + lhalf * 8;
    const uint32_t sOff = (uint32_t)(lrow * ROWB + lhalf * 16);

#define LOAD_STAGE(KT, BUF)                                                    \
    do {                                                                       \
        const uint32_t sbase_ = sb + (BUF) * STAGEB + sOff;                    \
        const size_t kk_ = (size_t)(KT) * KSTEP;                               \
        cp16(sbase_ + 0 * TILEB, g_Ah + gOffA + kk_);                          \
        cp16(sbase_ + 1 * TILEB, g_Al + gOffA + kk_);                          \
        cp16(sbase_ + 2 * TILEB, g_Bh + gOffB + kk_);                          \
        cp16(sbase_ + 3 * TILEB, g_Bl + gOffB + kk_);                          \
        cp_commit();                                                           \
    } while (0)

    float d[2][8][4];
#pragma unroll
    for (int mi = 0; mi < 2; mi++)
#pragma unroll
        for (int ni = 0; ni < 8; ni++)
#pragma unroll
            for (int q = 0; q < 4; q++) d[mi][ni][q] = 0.0f;

    LOAD_STAGE(0, 0);
    LOAD_STAGE(1, 1);
    LOAD_STAGE(2, 2);

    // fragment address offsets within a stage (constant across k loop)
    // A frag: rows warpM*32 + mi*16 + {g, 8+g}, k bytes tig*4 and +16
    const uint32_t aRow0 = (uint32_t)((warpM * 32 + g) * ROWB + tig * 4);
    const uint32_t bRow0 = (uint32_t)((warpN * 64 + g) * ROWB + tig * 4);

    for (int kt = 0; kt < NK; kt++) {
        cp_wait<2>();
        __syncthreads();
        if (kt + PIPE - 1 < NK) LOAD_STAGE(kt + PIPE - 1, (kt + PIPE - 1) & (PIPE - 1));
        else cp_commit();   // keep group count uniform so wait<2> stays correct

        const uint32_t stage = sb + (uint32_t)(kt & (PIPE - 1)) * STAGEB;
        const uint32_t Ah_s = stage + 0 * TILEB;
        const uint32_t Al_s = stage + 1 * TILEB;
        const uint32_t Bh_s = stage + 2 * TILEB;
        const uint32_t Bl_s = stage + 3 * TILEB;

        uint32_t ah[2][4], al[2][4];
#pragma unroll
        for (int mi = 0; mi < 2; mi++) {
            const uint32_t r0 = aRow0 + mi * 16 * ROWB;
            const uint32_t r1 = r0 + 8 * ROWB;
            ah[mi][0] = lds32(Ah_s + r0);      ah[mi][1] = lds32(Ah_s + r1);
            ah[mi][2] = lds32(Ah_s + r0 + 16); ah[mi][3] = lds32(Ah_s + r1 + 16);
            al[mi][0] = lds32(Al_s + r0);      al[mi][1] = lds32(Al_s + r1);
            al[mi][2] = lds32(Al_s + r0 + 16); al[mi][3] = lds32(Al_s + r1 + 16);
        }
#pragma unroll
        for (int ni = 0; ni < 8; ni++) {
            const uint32_t rb = bRow0 + ni * 8 * ROWB;
            const uint32_t bh0 = lds32(Bh_s + rb), bh1 = lds32(Bh_s + rb + 16);
            const uint32_t bl0 = lds32(Bl_s + rb), bl1 = lds32(Bl_s + rb + 16);
            mma16816(d[0][ni], ah[0], bh0, bh1);
            mma16816(d[1][ni], ah[1], bh0, bh1);
            mma16816(d[0][ni], ah[0], bl0, bl1);
            mma16816(d[1][ni], ah[1], bl0, bl1);
            mma16816(d[0][ni], al[0], bh0, bh1);
            mma16816(d[1][ni], al[1], bh0, bh1);
        }
    }
    __syncthreads();   // before reusing smem for reduction

    // ---- fused epilogue: s = sum_n tanh(C + bh)*Wv over this warp's 64 cols ----
    float s[2][2] = {{0.f, 0.f}, {0.f, 0.f}};
#pragma unroll
    for (int ni = 0; ni < 8; ni++) {
        const int n0 = colBase + warpN * 64 + ni * 8 + 2 * tig;
        const float bb0 = __ldg(bh + n0), bb1 = __ldg(bh + n0 + 1);
        const float w0  = __ldg(Wv + n0), w1  = __ldg(Wv + n0 + 1);
#pragma unroll
        for (int mi = 0; mi < 2; mi++) {
            s[mi][0] = fmaf(fast_tanh(d[mi][ni][0] + bb0), w0, s[mi][0]);
            s[mi][0] = fmaf(fast_tanh(d[mi][ni][1] + bb1), w1, s[mi][0]);
            s[mi][1] = fmaf(fast_tanh(d[mi][ni][2] + bb0), w0, s[mi][1]);
            s[mi][1] = fmaf(fast_tanh(d[mi][ni][3] + bb1), w1, s[mi][1]);
        }
    }
    // reduce across the 4 lanes of each group (they share the same rows)
#pragma unroll
    for (int off = 1; off <= 2; off <<= 1) {
#pragma unroll
        for (int mi = 0; mi < 2; mi++) {
            s[mi][0] += __shfl_xor_sync(0xFFFFFFFFu, s[mi][0], off);
            s[mi][1] += __shfl_xor_sync(0xFFFFFFFFu, s[mi][1], off);
        }
    }
    float* red = (float*)smem;   // [128][2]
    if (tig == 0) {
#pragma unroll
        for (int mi = 0; mi < 2; mi++) {
            red[(warpM * 32 + mi * 16 + g) * 2 + warpN]     = s[mi][0];
            red[(warpM * 32 + mi * 16 + 8 + g) * 2 + warpN] = s[mi][1];
        }
    }
    __syncthreads();
    if (tid < BM)
        g_partial[(size_t)(rowBase + tid) * NBLK + blockIdx.x] = red[tid * 2] + red[tid * 2 + 1];
#undef LOAD_STAGE
}

// ---------------------------------------------------------------------------
// Kernel 2: per-batch softmax over T=512 (dec/bias terms cancel in softmax)
// ---------------------------------------------------------------------------
__global__ void k_softmax(float* __restrict__ attn_out)
{
    const int b = blockIdx.x;
    const int t = threadIdx.x;
    __shared__ float sm[T_];

    const float* p = g_partial + ((size_t)b * T_ + t) * NBLK;
    float sc = 0.0f;
#pragma unroll
    for (int i = 0; i < NBLK; i++) sc += p[i];

    sm[t] = sc;
    __syncthreads();
    for (int o = T_ / 2; o > 0; o >>= 1) {
        if (t < o) sm[t] = fmaxf(sm[t], sm[t + o]);
        __syncthreads();
    }
    const float mx = sm[0];
    __syncthreads();

    const float e = expf(sc - mx);
    sm[t] = e;
    __syncthreads();
    for (int o = T_ / 2; o > 0; o >>= 1) {
        if (t < o) sm[t] += sm[t + o];
        __syncthreads();
    }
    attn_out[b * T_ + t] = e / sm[0];
}

// ---------------------------------------------------------------------------
// Kernel 3: context[b,h] = sum_t attn[b,t] * enc[b,t,h]
// ---------------------------------------------------------------------------
__global__ __launch_bounds__(256)
void k_context(const float* __restrict__ enc,
               const float* __restrict__ attn,
               float* __restrict__ ctx)
{
    const int b = blockIdx.y;
    const int h = blockIdx.x * 256 + threadIdx.x;

    __shared__ float a[T_];
    a[threadIdx.x]       = attn[b * T_ + threadIdx.x];
    a[threadIdx.x + 256] = attn[b * T_ + 256 + threadIdx.x];
    __syncthreads();

    const float* e = enc + (size_t)b * T_ * H_ + h;
    float acc0 = 0.f, acc1 = 0.f, acc2 = 0.f, acc3 = 0.f;
    float acc4 = 0.f, acc5 = 0.f, acc6 = 0.f, acc7 = 0.f;
#pragma unroll 2
    for (int t = 0; t < T_; t += 8) {
        acc0 = fmaf(a[t + 0], e[(t + 0) * H_], acc0);
        acc1 = fmaf(a[t + 1], e[(t + 1) * H_], acc1);
        acc2 = fmaf(a[t + 2], e[(t + 2) * H_], acc2);
        acc3 = fmaf(a[t + 3], e[(t + 3) * H_], acc3);
        acc4 = fmaf(a[t + 4], e[(t + 4) * H_], acc4);
        acc5 = fmaf(a[t + 5], e[(t + 5) * H_], acc5);
        acc6 = fmaf(a[t + 6], e[(t + 6) * H_], acc6);
        acc7 = fmaf(a[t + 7], e[(t + 7) * H_], acc7);
    }
    ctx[b * H_ + h] = ((acc0 + acc1) + (acc2 + acc3)) + ((acc4 + acc5) + (acc6 + acc7));
}

// ---------------------------------------------------------------------------
// Launch. Inputs: dec_hidden, enc_output, Wh, bh, Ws, bs, Wv, bv.
// dec/Ws/bs/bv cancel inside softmax. Output: [ctx (64*1024) | attn (64*512)].
// ---------------------------------------------------------------------------
extern "C" void kernel_launch(void* const* d_in, const int* in_sizes, int n_in,
                              void* d_out, int out_size)
{
    (void)in_sizes; (void)n_in; (void)out_size;
    const float* enc = (const float*)d_in[1];
    const float* Wh  = (const float*)d_in[2];
    const float* bh  = (const float*)d_in[3];
    const float* Wv  = (const float*)d_in[6];

    float* out  = (float*)d_out;
    float* ctx  = out;
    float* attn = out + B_ * H_;

    static bool attr_done = false;
    if (!attr_done) {
        cudaFuncSetAttribute(k_gemm_mma, cudaFuncAttributeMaxDynamicSharedMemorySize, SMEM_TOTAL);
        attr_done = true;
    }

    k_convA<<<(M_ * H_) / (256 * 4), 256>>>(enc);
    k_convB<<<dim3(U_ / 32, H_ / 32), dim3(32, 8)>>>(Wh);
    k_gemm_mma<<<dim3(NBLK, M_ / BM), 256, SMEM_TOTAL>>>(bh, Wv);
    k_softmax<<<B_, T_>>>(attn);
    k_context<<<dim3(H_ / 256, B_), 256>>>(enc, attn, ctx);
}

// round 4
// speedup vs baseline: 2.1174x; 1.1408x over previous
#include <cuda_runtime.h>
#include <cuda_bf16.h>
#include <cstdint>
#include <math.h>

// ---------------- problem constants ----------------
#define B_  64
#define T_  512
#define H_  1024
#define U_  1024
#define M_  (B_ * T_)          // 32768
#define NBLK 8                 // U_/128 column blocks

// ---------------- GEMM tiling ----------------
#define BM 128
#define BN 128
#define KSTEP 16
#define NK (H_ / KSTEP)        // 64 k-steps
#define TILEB 4096             // 128 rows * 32B (swizzled, no pad)
#define STAGEB (4 * TILEB)     // Ah, Al, Bh, Bl = 16 KB per stage
#define PIPE 4
#define SMEM_TOTAL (PIPE * STAGEB)   // 65536 B

// ---------------- device scratch ----------------
__device__ __nv_bfloat16 g_Ah[(size_t)M_ * H_];
__device__ __nv_bfloat16 g_Al[(size_t)M_ * H_];
__device__ __nv_bfloat16 g_Bh[(size_t)U_ * H_];   // Wh^T as [n][k]
__device__ __nv_bfloat16 g_Bl[(size_t)U_ * H_];
__device__ float g_partial[(size_t)M_ * NBLK];

// ---------------- helpers ----------------
__device__ __forceinline__ uint32_t smem_u32(const void* p) {
    uint32_t a;
    asm("{ .reg .u64 t; cvta.to.shared.u64 t, %1; cvt.u32.u64 %0, t; }" : "=r"(a) : "l"(p));
    return a;
}
__device__ __forceinline__ void cp16(uint32_t dst, const void* src) {
    asm volatile("cp.async.cg.shared.global [%0], [%1], 16;" :: "r"(dst), "l"(src));
}
__device__ __forceinline__ void cp_commit() { asm volatile("cp.async.commit_group;" ::: "memory"); }
template <int N_> __device__ __forceinline__ void cp_wait() {
    asm volatile("cp.async.wait_group %0;" :: "n"(N_) : "memory");
}
__device__ __forceinline__ void ldsm4(uint32_t* r, uint32_t a) {
    asm volatile("ldmatrix.sync.aligned.m8n8.x4.shared.b16 {%0,%1,%2,%3}, [%4];"
                 : "=r"(r[0]), "=r"(r[1]), "=r"(r[2]), "=r"(r[3]) : "r"(a));
}
__device__ __forceinline__ void mma16816(float* d, const uint32_t* a, uint32_t b0, uint32_t b1) {
    asm volatile(
        "mma.sync.aligned.m16n8k16.row.col.f32.bf16.bf16.f32 "
        "{%0,%1,%2,%3},{%4,%5,%6,%7},{%8,%9},{%0,%1,%2,%3};"
        : "+f"(d[0]), "+f"(d[1]), "+f"(d[2]), "+f"(d[3])
        : "r"(a[0]), "r"(a[1]), "r"(a[2]), "r"(a[3]), "r"(b0), "r"(b1));
}
__device__ __forceinline__ float fast_tanh(float x) {
    float ax = fabsf(x);
    float e  = __expf(2.0f * ax);
    float r  = 1.0f - __fdividef(2.0f, e + 1.0f);
    return copysignf(r, x);
}
// 16B-chunk swizzle within a [128 x 32B] tile: conflict-free for LDSM phases
// (8 rows, fixed c) and for cp.async store phases (4 rows x 2 c).
__device__ __forceinline__ uint32_t tile_off(int row, int c) {
    const int r8  = row & 7;
    const int idx = r8 * 2 + (c ^ ((r8 >> 2) & 1));
    return (uint32_t)((row >> 3) * 256 + idx * 16);
}

// ---------------------------------------------------------------------------
// Kernel 0a: split enc fp32 -> bf16 hi/lo
// ---------------------------------------------------------------------------
__global__ __launch_bounds__(256)
void k_convA(const float* __restrict__ A)
{
    size_t i = ((size_t)blockIdx.x * 256 + threadIdx.x) * 4;
    float4 v = *(const float4*)(A + i);
    __nv_bfloat16 h0 = __float2bfloat16(v.x), h1 = __float2bfloat16(v.y);
    __nv_bfloat16 h2 = __float2bfloat16(v.z), h3 = __float2bfloat16(v.w);
    __nv_bfloat16 l0 = __float2bfloat16(v.x - __bfloat162float(h0));
    __nv_bfloat16 l1 = __float2bfloat16(v.y - __bfloat162float(h1));
    __nv_bfloat16 l2 = __float2bfloat16(v.z - __bfloat162float(h2));
    __nv_bfloat16 l3 = __float2bfloat16(v.w - __bfloat162float(h3));
    __nv_bfloat162* ph = (__nv_bfloat162*)(g_Ah + i);
    __nv_bfloat162* pl = (__nv_bfloat162*)(g_Al + i);
    ph[0] = __nv_bfloat162(h0, h1); ph[1] = __nv_bfloat162(h2, h3);
    pl[0] = __nv_bfloat162(l0, l1); pl[1] = __nv_bfloat162(l2, l3);
}

// ---------------------------------------------------------------------------
// Kernel 0b: transpose+split Wh [K,N] fp32 -> g_Bh/g_Bl [N,K] bf16
// ---------------------------------------------------------------------------
__global__ __launch_bounds__(256)
void k_convB(const float* __restrict__ Wh)
{
    __shared__ float tile[32][33];
    const int k0 = blockIdx.y * 32, n0 = blockIdx.x * 32;
    const int tx = threadIdx.x, ty = threadIdx.y;   // 32 x 8
#pragma unroll
    for (int r = 0; r < 4; r++)
        tile[ty + r * 8][tx] = Wh[(size_t)(k0 + ty + r * 8) * U_ + n0 + tx];
    __syncthreads();
#pragma unroll
    for (int r = 0; r < 4; r++) {
        int n = n0 + ty + r * 8;
        int k = k0 + tx;
        float v = tile[tx][ty + r * 8];
        __nv_bfloat16 h = __float2bfloat16(v);
        __nv_bfloat16 l = __float2bfloat16(v - __bfloat162float(h));
        g_Bh[(size_t)n * H_ + k] = h;
        g_Bl[(size_t)n * H_ + k] = l;
    }
}

// ---------------------------------------------------------------------------
// Kernel 1: bf16 split GEMM (ldmatrix + mma.sync) with fused tanh-dot epilogue
// ---------------------------------------------------------------------------
__global__ __launch_bounds__(256, 2)
void k_gemm_mma(const float* __restrict__ bh, const float* __restrict__ Wv)
{
    extern __shared__ char smem[];
    const uint32_t sb = smem_u32(smem);

    const int tid  = threadIdx.x;
    const int warp = tid >> 5;
    const int lane = tid & 31;
    const int g    = lane >> 2;
    const int tig  = lane & 3;
    const int warpM = warp >> 1;      // 0..3  (32-row slab)
    const int warpN = warp & 1;       // 0..1  (64-col slab)

    const int rowBase = blockIdx.y * BM;
    const int colBase = blockIdx.x * BN;

    // ---- cp.async per-thread indices: one 16B chunk per tile ----
    const int lrow = tid >> 1;
    const int lc   = tid & 1;
    const size_t gRowA = (size_t)(rowBase + lrow) * H_ + lc * 8;
    const size_t gRowB = (size_t)(colBase + lrow) * H_ + lc * 8;
    const uint32_t sOff = tile_off(lrow, lc);

#define LOAD_STAGE(KT, BUF)                                                    \
    do {                                                                       \
        const uint32_t sbase_ = sb + (BUF) * STAGEB + sOff;                    \
        const size_t kk_ = (size_t)(KT) * KSTEP;                               \
        cp16(sbase_ + 0 * TILEB, g_Ah + gRowA + kk_);                          \
        cp16(sbase_ + 1 * TILEB, g_Al + gRowA + kk_);                          \
        cp16(sbase_ + 2 * TILEB, g_Bh + gRowB + kk_);                          \
        cp16(sbase_ + 3 * TILEB, g_Bl + gRowB + kk_);                          \
        cp_commit();                                                           \
    } while (0)

    // ---- ldmatrix per-lane addresses (offsets within a tile) ----
    const int sub = lane >> 3, q = lane & 7;
    // A (x4): sub0: rows+0 c0 | sub1: rows+8 c0 | sub2: rows+0 c1 | sub3: rows+8 c1
    uint32_t aOff[2];
#pragma unroll
    for (int mi = 0; mi < 2; mi++) {
        const int rowA = warpM * 32 + mi * 16 + ((sub & 1) ? 8 : 0) + q;
        aOff[mi] = tile_off(rowA, sub >> 1);
    }
    // B (x4, two ni): sub0: n+0 c0 | sub1: n+0 c1 | sub2: n+8 c0 | sub3: n+8 c1
    uint32_t bOff[4];
#pragma unroll
    for (int nip = 0; nip < 4; nip++) {
        const int rowB = warpN * 64 + nip * 16 + ((sub & 2) ? 8 : 0) + q;
        bOff[nip] = tile_off(rowB, sub & 1);
    }

    float d[2][8][4];
#pragma unroll
    for (int mi = 0; mi < 2; mi++)
#pragma unroll
        for (int ni = 0; ni < 8; ni++)
#pragma unroll
            for (int qq = 0; qq < 4; qq++) d[mi][ni][qq] = 0.0f;

    LOAD_STAGE(0, 0);
    LOAD_STAGE(1, 1);
    LOAD_STAGE(2, 2);

#pragma unroll 4
    for (int kt = 0; kt < NK; kt++) {
        cp_wait<2>();
        __syncthreads();
        if (kt + 3 < NK) LOAD_STAGE(kt + 3, (kt + 3) & (PIPE - 1));
        else cp_commit();   // keep group count uniform

        const uint32_t stage = sb + (uint32_t)(kt & (PIPE - 1)) * STAGEB;
        const uint32_t Ah_s = stage, Al_s = stage + TILEB;
        const uint32_t Bh_s = stage + 2 * TILEB, Bl_s = stage + 3 * TILEB;

        uint32_t ah[2][4], al[2][4];
        ldsm4(ah[0], Ah_s + aOff[0]);
        ldsm4(ah[1], Ah_s + aOff[1]);
        ldsm4(al[0], Al_s + aOff[0]);
        ldsm4(al[1], Al_s + aOff[1]);

#pragma unroll
        for (int nip = 0; nip < 4; nip++) {
            uint32_t b4h[4], b4l[4];
            ldsm4(b4h, Bh_s + bOff[nip]);
            ldsm4(b4l, Bl_s + bOff[nip]);
            const int n0 = nip * 2, n1 = nip * 2 + 1;
            mma16816(d[0][n0], ah[0], b4h[0], b4h[1]);
            mma16816(d[1][n0], ah[1], b4h[0], b4h[1]);
            mma16816(d[0][n0], al[0], b4h[0], b4h[1]);
            mma16816(d[1][n0], al[1], b4h[0], b4h[1]);
            mma16816(d[0][n0], ah[0], b4l[0], b4l[1]);
            mma16816(d[1][n0], ah[1], b4l[0], b4l[1]);
            mma16816(d[0][n1], ah[0], b4h[2], b4h[3]);
            mma16816(d[1][n1], ah[1], b4h[2], b4h[3]);
            mma16816(d[0][n1], al[0], b4h[2], b4h[3]);
            mma16816(d[1][n1], al[1], b4h[2], b4h[3]);
            mma16816(d[0][n1], ah[0], b4l[2], b4l[3]);
            mma16816(d[1][n1], ah[1], b4l[2], b4l[3]);
        }
    }
    __syncthreads();   // before reusing smem for reduction

    // ---- fused epilogue: s = sum_n tanh(C + bh)*Wv over this warp's 64 cols ----
    float s[2][2] = {{0.f, 0.f}, {0.f, 0.f}};
#pragma unroll
    for (int ni = 0; ni < 8; ni++) {
        const int n0 = colBase + warpN * 64 + ni * 8 + 2 * tig;
        const float bb0 = __ldg(bh + n0), bb1 = __ldg(bh + n0 + 1);
        const float w0  = __ldg(Wv + n0), w1  = __ldg(Wv + n0 + 1);
#pragma unroll
        for (int mi = 0; mi < 2; mi++) {
            s[mi][0] = fmaf(fast_tanh(d[mi][ni][0] + bb0), w0, s[mi][0]);
            s[mi][0] = fmaf(fast_tanh(d[mi][ni][1] + bb1), w1, s[mi][0]);
            s[mi][1] = fmaf(fast_tanh(d[mi][ni][2] + bb0), w0, s[mi][1]);
            s[mi][1] = fmaf(fast_tanh(d[mi][ni][3] + bb1), w1, s[mi][1]);
        }
    }
#pragma unroll
    for (int off = 1; off <= 2; off <<= 1) {
#pragma unroll
        for (int mi = 0; mi < 2; mi++) {
            s[mi][0] += __shfl_xor_sync(0xFFFFFFFFu, s[mi][0], off);
            s[mi][1] += __shfl_xor_sync(0xFFFFFFFFu, s[mi][1], off);
        }
    }
    float* red = (float*)smem;   // [128][2]
    if (tig == 0) {
#pragma unroll
        for (int mi = 0; mi < 2; mi++) {
            red[(warpM * 32 + mi * 16 + g) * 2 + warpN]     = s[mi][0];
            red[(warpM * 32 + mi * 16 + 8 + g) * 2 + warpN] = s[mi][1];
        }
    }
    __syncthreads();
    if (tid < BM)
        g_partial[(size_t)(rowBase + tid) * NBLK + blockIdx.x] = red[tid * 2] + red[tid * 2 + 1];
#undef LOAD_STAGE
}

// ---------------------------------------------------------------------------
// Kernel 2: per-batch softmax over T=512 (dec/bias terms cancel in softmax)
// ---------------------------------------------------------------------------
__global__ void k_softmax(float* __restrict__ attn_out)
{
    const int b = blockIdx.x;
    const int t = threadIdx.x;
    __shared__ float sm[T_];

    const float* p = g_partial + ((size_t)b * T_ + t) * NBLK;
    float sc = 0.0f;
#pragma unroll
    for (int i = 0; i < NBLK; i++) sc += p[i];

    sm[t] = sc;
    __syncthreads();
    for (int o = T_ / 2; o > 0; o >>= 1) {
        if (t < o) sm[t] = fmaxf(sm[t], sm[t + o]);
        __syncthreads();
    }
    const float mx = sm[0];
    __syncthreads();

    const float e = expf(sc - mx);
    sm[t] = e;
    __syncthreads();
    for (int o = T_ / 2; o > 0; o >>= 1) {
        if (t < o) sm[t] += sm[t + o];
        __syncthreads();
    }
    attn_out[b * T_ + t] = e / sm[0];
}

// ---------------------------------------------------------------------------
// Kernel 3: context[b,h] = sum_t attn[b,t] * enc[b,t,h]
// ---------------------------------------------------------------------------
__global__ __launch_bounds__(256)
void k_context(const float* __restrict__ enc,
               const float* __restrict__ attn,
               float* __restrict__ ctx)
{
    const int b = blockIdx.y;
    const int h = blockIdx.x * 256 + threadIdx.x;

    __shared__ float a[T_];
    a[threadIdx.x]       = attn[b * T_ + threadIdx.x];
    a[threadIdx.x + 256] = attn[b * T_ + 256 + threadIdx.x];
    __syncthreads();

    const float* e = enc + (size_t)b * T_ * H_ + h;
    float acc0 = 0.f, acc1 = 0.f, acc2 = 0.f, acc3 = 0.f;
    float acc4 = 0.f, acc5 = 0.f, acc6 = 0.f, acc7 = 0.f;
#pragma unroll 2
    for (int t = 0; t < T_; t += 8) {
        acc0 = fmaf(a[t + 0], e[(t + 0) * H_], acc0);
        acc1 = fmaf(a[t + 1], e[(t + 1) * H_], acc1);
        acc2 = fmaf(a[t + 2], e[(t + 2) * H_], acc2);
        acc3 = fmaf(a[t + 3], e[(t + 3) * H_], acc3);
        acc4 = fmaf(a[t + 4], e[(t + 4) * H_], acc4);
        acc5 = fmaf(a[t + 5], e[(t + 5) * H_], acc5);
        acc6 = fmaf(a[t + 6], e[(t + 6) * H_], acc6);
        acc7 = fmaf(a[t + 7], e[(t + 7) * H_], acc7);
    }
    ctx[b * H_ + h] = ((acc0 + acc1) + (acc2 + acc3)) + ((acc4 + acc5) + (acc6 + acc7));
}

// ---------------------------------------------------------------------------
// Launch. Inputs: dec_hidden, enc_output, Wh, bh, Ws, bs, Wv, bv.
// dec/Ws/bs/bv cancel inside softmax. Output: [ctx (64*1024) | attn (64*512)].
// ---------------------------------------------------------------------------
extern "C" void kernel_launch(void* const* d_in, const int* in_sizes, int n_in,
                              void* d_out, int out_size)
{
    (void)in_sizes; (void)n_in; (void)out_size;
    const float* enc = (const float*)d_in[1];
    const float* Wh  = (const float*)d_in[2];
    const float* bh  = (const float*)d_in[3];
    const float* Wv  = (const float*)d_in[6];

    float* out  = (float*)d_out;
    float* ctx  = out;
    float* attn = out + B_ * H_;

    static bool attr_done = false;
    if (!attr_done) {
        cudaFuncSetAttribute(k_gemm_mma, cudaFuncAttributeMaxDynamicSharedMemorySize, SMEM_TOTAL);
        attr_done = true;
    }

    k_convA<<<(M_ * H_) / (256 * 4), 256>>>(enc);
    k_convB<<<dim3(U_ / 32, H_ / 32), dim3(32, 8)>>>(Wh);
    k_gemm_mma<<<dim3(NBLK, M_ / BM), 256, SMEM_TOTAL>>>(bh, Wv);
    k_softmax<<<B_, T_>>>(attn);
    k_context<<<dim3(H_ / 256, B_), 256>>>(enc, attn, ctx);
}